// round 4
// baseline (speedup 1.0000x reference)
#include <cuda_runtime.h>
#include <cstdint>

#define NGRP    128
#define T_TOT   512
#define TILE_T  8
#define NTILE   64            // 512 / 8
#define XS      3             // xbuf slots
#define RS      8             // gate-ring slots
#define PROD_T  512
#define CONS_T  64
#define NTHREADS 576

#define XROW4       56                        // float4 per xbuf row (50 data + pad; mult of 8)
#define XSLOT_F4    (32 * XROW4)              // 1792 float4 per slot
#define RING_FLOATS (RS * TILE_T * 256)       // 16384 floats = 64 KB
#define SMEM_BYTES  (RING_FLOATS * 4 + XS * XSLOT_F4 * 16)   // 64KB + 84KB = 148KB

__device__ __forceinline__ float tanha(float v) {
    float y;
    asm("tanh.approx.f32 %0, %1;" : "=f"(y) : "f"(v));
    return y;
}

__device__ __forceinline__ uint32_t smem_u32(const void* p) {
    uint32_t a;
    asm("{ .reg .u64 t; cvta.to.shared.u64 t, %1; cvt.u32.u64 %0, t; }" : "=r"(a) : "l"(p));
    return a;
}

#define MBAR_INIT(addr, cnt) \
    asm volatile("mbarrier.init.shared.b64 [%0], %1;" :: "r"(addr), "r"(cnt) : "memory")
#define MBAR_ARRIVE(addr) \
    asm volatile("mbarrier.arrive.release.cta.shared::cta.b64 _, [%0];" :: "r"(addr) : "memory")

__device__ __forceinline__ void mbar_wait_parity(uint32_t mbar, uint32_t parity) {
    uint32_t done;
    asm volatile(
        "{\n\t.reg .pred p;\n\t"
        "mbarrier.try_wait.parity.acquire.cta.shared::cta.b64 p, [%1], %2;\n\t"
        "selp.b32 %0, 1, 0, p;\n\t}"
        : "=r"(done) : "r"(mbar), "r"(parity) : "memory");
    if (!done) {
        asm volatile(
            "{\n\t.reg .pred P1;\n\t"
            "W_%=:\n\t"
            "mbarrier.try_wait.parity.acquire.cta.shared::cta.b64 P1, [%0], %1, 0x989680;\n\t"
            "@P1 bra.uni D_%=;\n\t"
            "bra.uni W_%=;\n\t"
            "D_%=:\n\t}"
            :: "r"(mbar), "r"(parity) : "memory");
    }
}

// Barrier index layout inside bars[]: xfull[0..2], xempty[3..5], rfull[6..13], rempty[14..21]
#define BX_FULL(s)  ((s) * 8)
#define BX_EMPTY(s) ((XS + (s)) * 8)
#define BR_FULL(s)  ((2 * XS + (s)) * 8)
#define BR_EMPTY(s) ((2 * XS + RS + (s)) * 8)

// ---------------------------------------------------------------------------
// Gate loop: one warp per (LSTM L, t-pair P). Thread handles batches = lane,
// timesteps 2P and 2P+1 of each 8-t slot. NF/P compile-time -> static offsets.
// ---------------------------------------------------------------------------
template <int NF, int P>
__device__ __forceinline__ void gate_loop(
    const float4* __restrict__ xb4, float* __restrict__ ring, uint32_t bar,
    int l, const float* __restrict__ Wih, const float* __restrict__ bp)
{
    constexpr int FOFF = (NF == 13) ? 12 : 0;
    constexpr int LOFF = (NF == 13) ? 128 : 0;

    float w[4][13], bb[4];
    #pragma unroll
    for (int g = 0; g < 4; g++) {
        float sc = (g == 2) ? 1.0f : 0.5f;
        bb[g] = bp[g] * sc;
        #pragma unroll
        for (int f = 0; f < NF; f++) w[g][f] = Wih[g * NF + f] * sc;
    }

    const int xl = l & 7;
    int gxs = 0, gxp = 0;   // xfull wait state
    int grs = 0, grp = 1;   // rempty wait state (starts flipped)

    for (int k = 0; k < NTILE; k++) {
        mbar_wait_parity(bar + BX_FULL(gxs), (uint32_t)gxp);
        mbar_wait_parity(bar + BR_EMPTY(grs), (uint32_t)grp);

        const float4* xr = xb4 + (size_t)gxs * XSLOT_F4 + (size_t)l * XROW4;

        #pragma unroll
        for (int half = 0; half < 2; half++) {
            constexpr int NQ0 = ((((2 * P) * 25 + FOFF) & 3) + NF + 3) >> 2;
            constexpr int NQ1 = ((((2 * P + 1) * 25 + FOFF) & 3) + NF + 3) >> 2;
            const int tloc = 2 * P + half;
            const int fidx = tloc * 25 + FOFF;
            const int q0 = fidx >> 2;
            const int o  = fidx & 3;
            const int nq = half ? NQ1 : NQ0;

            float xa[16];
            #pragma unroll
            for (int j = 0; j < 4; j++) {
                if (j < nq) {
                    float4 t = xr[(q0 + j) ^ xl];
                    xa[4 * j + 0] = t.x; xa[4 * j + 1] = t.y;
                    xa[4 * j + 2] = t.z; xa[4 * j + 3] = t.w;
                }
            }

            float a0 = bb[0], a1 = bb[1], a2 = bb[2], a3 = bb[3];
            #pragma unroll
            for (int f = 0; f < NF; f++) {
                float v = xa[o + f];
                a0 = fmaf(w[0][f], v, a0);
                a1 = fmaf(w[1][f], v, a1);
                a2 = fmaf(w[2][f], v, a2);
                a3 = fmaf(w[3][f], v, a3);
            }

            *(float4*)(ring + (size_t)(grs * TILE_T + tloc) * 256 + LOFF + l * 4) =
                make_float4(a0, a1, a2, a3);
        }

        MBAR_ARRIVE(bar + BX_EMPTY(gxs));   // done reading xbuf slot
        MBAR_ARRIVE(bar + BR_FULL(grs));    // ring slot filled (release orders STS)

        if (++gxs == XS) { gxs = 0; gxp ^= 1; }
        if (++grs == RS) { grs = 0; grp ^= 1; }
    }
}

// ---------------------------------------------------------------------------
__global__ __launch_bounds__(NTHREADS, 1) void fused_kernel(
    const float* __restrict__ x,
    const float* __restrict__ Wih1, const float* __restrict__ Whh1, const float* __restrict__ b1,
    const float* __restrict__ Wih2, const float* __restrict__ Whh2, const float* __restrict__ b2,
    const float* __restrict__ Wout, const float* __restrict__ bout,
    float* __restrict__ out)
{
    extern __shared__ float smem[];
    float*  ring = smem;                             // [RS][TILE_T][256]
    float4* xb4  = (float4*)(smem + RING_FLOATS);    // [XS][32][XROW4]

    __shared__ __align__(8) uint64_t bars[2 * XS + 2 * RS];
    __shared__ float h2s[32];

    const int tid = threadIdx.x;
    const int wid = tid >> 5;
    const int bg  = blockIdx.x;
    const uint32_t bar = smem_u32(bars);

    if (tid == 0) {
        #pragma unroll
        for (int s = 0; s < XS; s++) {
            MBAR_INIT(bar + BX_FULL(s),  PROD_T / 2);  // 256 stage threads
            MBAR_INIT(bar + BX_EMPTY(s), PROD_T / 2);  // 256 gate threads
        }
        #pragma unroll
        for (int s = 0; s < RS; s++) {
            MBAR_INIT(bar + BR_FULL(s),  PROD_T / 2);  // 256 gate threads
            MBAR_INIT(bar + BR_EMPTY(s), CONS_T);      // 64 consumer threads
        }
    }
    __syncthreads();

    if (wid < 8) {
        // ================= STAGE WARPS: LDG float4 -> swizzled STS ============
        const int sj = tid;                            // 0..255
        const float4* xg = (const float4*)x;
        const size_t rowbase = (size_t)bg * 32 * 3200;

        float4 rb[2][7];

        #define LDG_SLOT(K, R) do {                                               \
            _Pragma("unroll")                                                     \
            for (int m = 0; m < 7; m++) {                                         \
                int i = m * 256 + sj;                                             \
                if (i < 1600) {                                                   \
                    int b = i / 50, q = i - b * 50;                               \
                    (R)[m] = xg[rowbase + (size_t)b * 3200 + (K) * 50 + q];       \
                }                                                                 \
            } } while (0)

        #define STS_SLOT(S, R) do {                                               \
            float4* dst = xb4 + (size_t)(S) * XSLOT_F4;                           \
            _Pragma("unroll")                                                     \
            for (int m = 0; m < 7; m++) {                                         \
                int i = m * 256 + sj;                                             \
                if (i < 1600) {                                                   \
                    int b = i / 50, q = i - b * 50;                               \
                    dst[(size_t)b * XROW4 + (q ^ (b & 7))] = (R)[m];              \
                }                                                                 \
            } } while (0)

        LDG_SLOT(0, rb[0]);
        int xs = 0, xp = 1;
        for (int k = 0; k < NTILE; k++) {
            if (k + 1 < NTILE) LDG_SLOT(k + 1, rb[(k + 1) & 1]);
            mbar_wait_parity(bar + BX_EMPTY(xs), (uint32_t)xp);
            STS_SLOT(xs, rb[k & 1]);
            MBAR_ARRIVE(bar + BX_FULL(xs));
            if (++xs == XS) { xs = 0; xp ^= 1; }
        }
        #undef LDG_SLOT
        #undef STS_SLOT
    } else if (wid < 16) {
        // ================= GATE WARPS =========================================
        const int gw = wid - 8;
        const int L  = gw & 1;       // 0: LSTM1, 1: LSTM2
        const int p  = gw >> 1;      // t-pair 0..3
        const int l  = tid & 31;
        if (L == 0) {
            switch (p) {
                case 0: gate_loop<12, 0>(xb4, ring, bar, l, Wih1, b1); break;
                case 1: gate_loop<12, 1>(xb4, ring, bar, l, Wih1, b1); break;
                case 2: gate_loop<12, 2>(xb4, ring, bar, l, Wih1, b1); break;
                default: gate_loop<12, 3>(xb4, ring, bar, l, Wih1, b1); break;
            }
        } else {
            switch (p) {
                case 0: gate_loop<13, 0>(xb4, ring, bar, l, Wih2, b2); break;
                case 1: gate_loop<13, 1>(xb4, ring, bar, l, Wih2, b2); break;
                case 2: gate_loop<13, 2>(xb4, ring, bar, l, Wih2, b2); break;
                default: gate_loop<13, 3>(xb4, ring, bar, l, Wih2, b2); break;
            }
        }
    } else {
        // ================= CONSUMER: serial recurrence ========================
        const int ctid = tid - PROD_T;
        const int cw   = ctid >> 5;  // 0: LSTM1, 1: LSTM2
        const int lane = ctid & 31;

        const float* Whh = cw ? Whh2 : Whh1;
        const float whi = Whh[0] * 0.5f;
        const float whf = Whh[1] * 0.5f;
        const float whg = Whh[2];
        const float who = Whh[3] * 0.5f;

        float h = 0.0f, c = 0.0f;
        int rs = 0, rp = 0;

        for (int k = 0; k < NTILE; k++) {
            mbar_wait_parity(bar + BR_FULL(rs), (uint32_t)rp);

            const float4* zp = (const float4*)&ring[(size_t)(rs * TILE_T) * 256 + cw * 128 + lane * 4];
            float4 z = zp[0];
            #pragma unroll
            for (int d = 0; d < TILE_T; d++) {
                float4 zn = z;
                if (d + 1 < TILE_T) zn = zp[(d + 1) * 64];

                float zi = fmaf(whi, h, z.x);
                float zf = fmaf(whf, h, z.y);
                float zg = fmaf(whg, h, z.z);
                float zo = fmaf(who, h, z.w);

                float gi = fmaf(0.5f, tanha(zi), 0.5f);
                float gf = fmaf(0.5f, tanha(zf), 0.5f);
                float gg = tanha(zg);
                float go = fmaf(0.5f, tanha(zo), 0.5f);

                c = fmaf(gf, c, gi * gg);
                h = go * tanha(c);
                z = zn;
            }
            MBAR_ARRIVE(bar + BR_EMPTY(rs));
            if (++rs == RS) { rs = 0; rp ^= 1; }
        }

        if (cw == 1) h2s[lane] = h;
        asm volatile("bar.sync 2, %0;" :: "n"(CONS_T) : "memory");
        if (cw == 0) {
            float h2 = h2s[lane];
            float y = fmaf(Wout[0], h, fmaf(Wout[1], h2, bout[0]));
            out[bg * 32 + lane] = 1.0f / (1.0f + __expf(-y));
        }
    }
}

// ---------------------------------------------------------------------------
extern "C" void kernel_launch(void* const* d_in, const int* in_sizes, int n_in,
                              void* d_out, int out_size)
{
    const float* x    = (const float*)d_in[0];
    const float* Wih1 = (const float*)d_in[1];
    const float* Whh1 = (const float*)d_in[2];
    const float* b1   = (const float*)d_in[3];
    const float* Wih2 = (const float*)d_in[4];
    const float* Whh2 = (const float*)d_in[5];
    const float* b2   = (const float*)d_in[6];
    const float* Wout = (const float*)d_in[7];
    const float* bout = (const float*)d_in[8];

    cudaFuncSetAttribute(fused_kernel, cudaFuncAttributeMaxDynamicSharedMemorySize, SMEM_BYTES);
    fused_kernel<<<NGRP, NTHREADS, SMEM_BYTES>>>(
        x, Wih1, Whh1, b1, Wih2, Whh2, b2, Wout, bout, (float*)d_out);
}